// round 4
// baseline (speedup 1.0000x reference)
#include <cuda_runtime.h>

typedef unsigned long long ull;

#define BATCH  4096
#define TSTEPS 1024
#define EMD    128
#define CELL   128
#define G4     512
#define KTOT   256
#define DOUT   5
#define NCTA   128
#define ROWS   32
#define NTHR   512
#define TILEK  16
#define NTILES 16
#define WBUF   (TILEK * G4)     /* 8192 floats per buffer */
#define A2S    34               /* A2 stride per k, in ull units = 272B */
#define GST    516              /* GACT row stride in floats = 2064B */

#define HOFF ((size_t)BATCH * TSTEPS * DOUT)
#define COFF (HOFF + (size_t)BATCH * CELL)

// ---- shared memory layout (float offsets) ----
#define OFF_W    0                              /* 2 x 8192 = 16384            */
#define OFF_A2   (2 * WBUF)                     /* 16384; 256*34 ull = 17408 f */
#define OFF_GACT (OFF_A2 + KTOT * A2S * 2)      /* 33792; 32*516 = 16512       */
#define OFF_B    (OFF_GACT + ROWS * GST)        /* 50304; 512                  */
#define OFF_WE2  (OFF_B + G4)                   /* 50816; 256                  */
#define OFF_BE   (OFF_WE2 + 256)                /* 51072; 128                  */
#define OFF_WO   (OFF_BE + 128)                 /* 51200; 5*132 = 660          */
#define OFF_BO   (OFF_WO + DOUT * 132)          /* 51860; 12 (pad)             */
#define OFF_XB   (OFF_BO + 12)                  /* 51872 (8B aligned); 64      */
#define SMEM_FLOATS (OFF_XB + 64)               /* 51936                       */
#define SMEM_BYTES  (SMEM_FLOATS * 4)           /* 207744                      */

// ---- scratch (static device arrays; allocation-free) ----
__device__ float g_Wt[KTOT * G4];   // [k][gate] combined transposed weights
__device__ float g_b[G4];           // b_ih + b_hh

// ---- helpers ----
__device__ __forceinline__ unsigned smem_u32(const void* p) {
    return (unsigned)__cvta_generic_to_shared(p);
}
__device__ __forceinline__ ull ffma2(ull a, ull b, ull c) {
    ull d;
    asm("fma.rn.f32x2 %0, %1, %2, %3;" : "=l"(d) : "l"(a), "l"(b), "l"(c));
    return d;
}
__device__ __forceinline__ ull pack2(float x, float y) {
    ull r;
    asm("mov.b64 %0, {%1, %2};" : "=l"(r) : "f"(x), "f"(y));
    return r;
}
__device__ __forceinline__ float2 unpack2(ull v) {
    float2 r;
    asm("mov.b64 {%0, %1}, %2;" : "=f"(r.x), "=f"(r.y) : "l"(v));
    return r;
}
__device__ __forceinline__ float tanha_(float x) {
    float y;
    asm("tanh.approx.f32 %0, %1;" : "=f"(y) : "f"(x));
    return y;
}

#define CP_ASYNC16(dst, src) asm volatile("cp.async.cg.shared.global [%0], [%1], 16;" :: "r"(dst), "l"(src))
#define CP_COMMIT()          asm volatile("cp.async.commit_group;")
#define CP_WAIT0()           asm volatile("cp.async.wait_group 0;")

// ---- prep: fuse W_ih|W_hh into [k][g] transposed layout, fold biases ----
__global__ void prep_weights(const float* __restrict__ W_ih, const float* __restrict__ W_hh,
                             const float* __restrict__ b_ih, const float* __restrict__ b_hh) {
    int idx = blockIdx.x * blockDim.x + threadIdx.x;
    if (idx < KTOT * G4) {
        int k = idx >> 9, g = idx & 511;
        g_Wt[idx] = (k < EMD) ? W_ih[g * EMD + k] : W_hh[g * CELL + (k - EMD)];
    }
    if (idx < G4) g_b[idx] = b_ih[idx] + b_hh[idx];
}

// ---- persistent LSTM: CTA = 32 batch rows for all T steps ----
__global__ void __launch_bounds__(NTHR, 1) lstm_main(
    const float* __restrict__ x,
    const float* __restrict__ We, const float* __restrict__ be,
    const float* __restrict__ Wo, const float* __restrict__ bo,
    float* __restrict__ out)
{
    extern __shared__ float sm[];
    const int tid     = threadIdx.x;
    const int rowbase = blockIdx.x * ROWS;

    // GEMM thread map: 8 rows x 4 cols per thread (weight redundancy = 4)
    const int rg = tid >> 7;                 // 0..3  -> rows 8rg..8rg+7
    const int cg = tid & 127;                // 0..127-> cols 4cg..4cg+3
    // gate type of this thread's 4 cols (warp-uniform): 0:i 1:f 2:g 3:o
    const int gate = cg >> 5;
    const float actm = (gate == 2) ? 1.0f : 0.5f;   // pre-scale for tanh/sigmoid
    const float acta = (gate == 2) ? 1.0f : 0.5f;   // post-scale
    const float actb = (gate == 2) ? 0.0f : 0.5f;   // post-offset

    // epilogue thread map: cell j x 8 rows
    const int j  = tid >> 2;                 // 0..127
    const int rb = tid & 3;                  // rows rb + 4m
    // output-projection map
    const int yr = tid / DOUT, yd = tid - yr * DOUT;   // valid when tid < 160

    ull* const A2u = (ull*)(sm + OFF_A2);
    const float2* const sWe2 = (const float2*)(sm + OFF_WE2);
    const float2* const xb   = (const float2*)(sm + OFF_XB);

    // prologue: stage parameters, zero A2 (h half must be 0 at t=0)
    for (int i = tid; i < G4; i += NTHR)      sm[OFF_B + i]   = g_b[i];
    for (int i = tid; i < 2 * EMD; i += NTHR) sm[OFF_WE2 + i] = We[i];
    for (int i = tid; i < EMD; i += NTHR)     sm[OFF_BE + i]  = be[i];
    for (int i = tid; i < DOUT * CELL; i += NTHR)
        sm[OFF_WO + (i >> 7) * 132 + (i & 127)] = Wo[i];
    if (tid < 12) sm[OFF_BO + tid] = (tid < DOUT) ? bo[tid] : 0.f;
    for (int i = tid; i < KTOT * A2S * 2; i += NTHR) sm[OFF_A2 + i] = 0.f;

    float creg[8];
    #pragma unroll
    for (int m = 0; m < 8; ++m) creg[m] = 0.f;

    // prefetch weight tile 0 into buf0
    {
        const float* src = g_Wt + (tid << 2);
        unsigned dst = smem_u32(sm + OFF_W) + (tid << 4);
        #pragma unroll
        for (int m2 = 0; m2 < 4; ++m2)
            CP_ASYNC16(dst + m2 * 8192, src + m2 * 2048);
        CP_COMMIT();
    }
    __syncthreads();

    for (int t = 0; t < TSTEPS; ++t) {
        // ---- (A) stage x[rows][t] into smem ----
        if (tid < ROWS)
            ((float2*)(sm + OFF_XB))[tid] =
                ((const float2*)x)[(size_t)(rowbase + tid) * TSTEPS + t];
        __syncthreads();

        // ---- (C) embed MLP: e = relu(x @ We^T + be) -> A2[j][row] duplicated ----
        {
            float2 wej = sWe2[j];
            float  bej = sm[OFF_BE + j];
            #pragma unroll
            for (int m = 0; m < 8; ++m) {
                int row = rb + 4 * m;
                float2 xv = xb[row];
                float e = fmaf(xv.x, wej.x, fmaf(xv.y, wej.y, bej));
                e = fmaxf(e, 0.f);
                A2u[j * A2S + row] = pack2(e, e);
            }
        }

        // ---- (E) gate GEMM: acc[8 rows][4 cols] with packed f32x2 ----
        ull acc[16];
        {
            ulonglong2 bv = ((const ulonglong2*)(sm + OFF_B))[cg];
            #pragma unroll
            for (int r = 0; r < 8; ++r) { acc[2 * r] = bv.x; acc[2 * r + 1] = bv.y; }
        }

        #pragma unroll 1
        for (int ti = 0; ti < NTILES; ++ti) {
            CP_WAIT0();
            __syncthreads();
            {   // prefetch next tile (tile 0 of next step when ti==15)
                int nti = (ti + 1) & 15;
                if (ti < 15 || t + 1 < TSTEPS) {
                    const float* src = g_Wt + nti * WBUF + (tid << 2);
                    unsigned dst = smem_u32(sm + OFF_W + ((ti + 1) & 1) * WBUF) + (tid << 4);
                    #pragma unroll
                    for (int m2 = 0; m2 < 4; ++m2)
                        CP_ASYNC16(dst + m2 * 8192, src + m2 * 2048);
                    CP_COMMIT();
                }
            }
            const float* wb = sm + OFF_W + (ti & 1) * WBUF + (cg << 2);
            const ull*   ab = A2u + ti * TILEK * A2S + (rg << 3);
            #pragma unroll
            for (int kk = 0; kk < TILEK; ++kk) {
                const ull* ar = ab + kk * A2S;
                ulonglong2 wv  = *(const ulonglong2*)(wb + kk * G4);   // 4 cols, 16B/lane spread
                ulonglong2 a01 = *(const ulonglong2*)(ar + 0);         // broadcast
                ulonglong2 a23 = *(const ulonglong2*)(ar + 2);
                ulonglong2 a45 = *(const ulonglong2*)(ar + 4);
                ulonglong2 a67 = *(const ulonglong2*)(ar + 6);
                acc[0]  = ffma2(a01.x, wv.x, acc[0]);  acc[1]  = ffma2(a01.x, wv.y, acc[1]);
                acc[2]  = ffma2(a01.y, wv.x, acc[2]);  acc[3]  = ffma2(a01.y, wv.y, acc[3]);
                acc[4]  = ffma2(a23.x, wv.x, acc[4]);  acc[5]  = ffma2(a23.x, wv.y, acc[5]);
                acc[6]  = ffma2(a23.y, wv.x, acc[6]);  acc[7]  = ffma2(a23.y, wv.y, acc[7]);
                acc[8]  = ffma2(a45.x, wv.x, acc[8]);  acc[9]  = ffma2(a45.x, wv.y, acc[9]);
                acc[10] = ffma2(a45.y, wv.x, acc[10]); acc[11] = ffma2(a45.y, wv.y, acc[11]);
                acc[12] = ffma2(a67.x, wv.x, acc[12]); acc[13] = ffma2(a67.x, wv.y, acc[13]);
                acc[14] = ffma2(a67.y, wv.x, acc[14]); acc[15] = ffma2(a67.y, wv.y, acc[15]);
            }
        }

        // ---- (F) activations (1 MUFU.TANH each) -> GACT[row][g], STS.128 ----
        #pragma unroll
        for (int r = 0; r < 8; ++r) {
            float2 v0 = unpack2(acc[2 * r]);
            float2 v1 = unpack2(acc[2 * r + 1]);
            v0.x = fmaf(tanha_(v0.x * actm), acta, actb);
            v0.y = fmaf(tanha_(v0.y * actm), acta, actb);
            v1.x = fmaf(tanha_(v1.x * actm), acta, actb);
            v1.y = fmaf(tanha_(v1.y * actm), acta, actb);
            float* gr = sm + OFF_GACT + (8 * rg + r) * GST + (cg << 2);
            ulonglong2 s; s.x = pack2(v0.x, v0.y); s.y = pack2(v1.x, v1.y);
            *(ulonglong2*)gr = s;
        }
        __syncthreads();

        // ---- (G) combine: c' = f*c + i*g ; h' = o*tanh(c') -> A2 h half ----
        const bool last = (t == TSTEPS - 1);
        #pragma unroll
        for (int m = 0; m < 8; ++m) {
            int row = rb + 4 * m;
            const float* gr = sm + OFF_GACT + row * GST + j;
            float iv = gr[0], fv = gr[EMD], gv = gr[2 * EMD], ov = gr[3 * EMD];
            float cn = fmaf(fv, creg[m], iv * gv);
            creg[m] = cn;
            float hn = ov * tanha_(cn);
            A2u[(EMD + j) * A2S + row] = pack2(hn, hn);
            if (last) {
                out[HOFF + (size_t)(rowbase + row) * CELL + j] = hn;
                out[COFF + (size_t)(rowbase + row) * CELL + j] = cn;
            }
        }
        __syncthreads();

        // ---- (H) output projection: y = h' @ Wo^T + bo ----
        if (tid < ROWS * DOUT) {
            float s0 = sm[OFF_BO + yd], s1 = 0.f, s2 = 0.f, s3 = 0.f;
            const float* wr_ = sm + OFF_WO + yd * 132;
            const float* hp  = sm + OFF_A2 + EMD * A2S * 2 + yr * 2;  // low float of dup
            #pragma unroll 8
            for (int jj = 0; jj < CELL; jj += 4) {
                s0 = fmaf(hp[(jj + 0) * (A2S * 2)], wr_[jj + 0], s0);
                s1 = fmaf(hp[(jj + 1) * (A2S * 2)], wr_[jj + 1], s1);
                s2 = fmaf(hp[(jj + 2) * (A2S * 2)], wr_[jj + 2], s2);
                s3 = fmaf(hp[(jj + 3) * (A2S * 2)], wr_[jj + 3], s3);
            }
            out[((size_t)(rowbase + yr) * TSTEPS + t) * DOUT + yd] = (s0 + s1) + (s2 + s3);
        }
        // next step's (A) barrier orders xbuf rewrite; GEMM reads gated by the
        // ti=0 CP_WAIT0+__syncthreads; y-proj h-reads are disjoint from e-writes.
    }
    CP_WAIT0();   // drain in-flight prefetch before exit
}

extern "C" void kernel_launch(void* const* d_in, const int* in_sizes, int n_in,
                              void* d_out, int out_size) {
    const float* x    = (const float*)d_in[0];
    const float* We   = (const float*)d_in[1];
    const float* be   = (const float*)d_in[2];
    const float* W_ih = (const float*)d_in[3];
    const float* W_hh = (const float*)d_in[4];
    const float* b_ih = (const float*)d_in[5];
    const float* b_hh = (const float*)d_in[6];
    const float* Wo   = (const float*)d_in[7];
    const float* bo   = (const float*)d_in[8];
    float* out = (float*)d_out;

    cudaFuncSetAttribute(lstm_main, cudaFuncAttributeMaxDynamicSharedMemorySize, SMEM_BYTES);

    prep_weights<<<512, 256>>>(W_ih, W_hh, b_ih, b_hh);
    lstm_main<<<NCTA, NTHR, SMEM_BYTES>>>(x, We, be, Wo, bo, out);
}